// round 14
// baseline (speedup 1.0000x reference)
#include <cuda_runtime.h>
#include <float.h>

#define NA 8400
#define NB 64
#define NC 32
#define MAXD 100
#define CONF_T 0.25f
#define IOU_T 0.45f

#define NT1 256
#define NJ (NA / 4)

#define NT2 1024
#define NSLOT 9
#define CAP 512
#define NBINS 2048
#define BASEKEY 0x3E800000   // bits of 0.25f
#define FULLM 0xffffffffu

__device__ float4        g_box[NB * NA];
__device__ float         g_sc [NB * NA];
__device__ unsigned char g_cls[NB * NA];

// dynamic smem: float4 box[NA] | float area[NA] | u8 cls[NA] | u64 k[CAP] | int hist[NBINS]
//               | float4 accb[128] | float acca[128]
#define OFF_AREA (NA * 16)
#define OFF_CLS  (OFF_AREA + NA * 4)
#define OFF_K64  (OFF_CLS + NA)
#define OFF_HIST (OFF_K64 + CAP * 8)
#define OFF_ACCB (OFF_HIST + NBINS * 4)
#define OFF_ACCA (OFF_ACCB + 128 * 16)
#define SMEM2_BYTES (OFF_ACCA + 128 * 4)

// ---------------- Kernel 1: decode (unchanged; at memory roofline) ----------------
__global__ __launch_bounds__(NT1)
void decode_kernel(const float* __restrict__ in)
{
    const int j = blockIdx.x * NT1 + threadIdx.x;
    const int b = blockIdx.y;
    if (j >= NJ) return;
    const float* base = in + (size_t)b * (4 + NC) * NA;

    const float4 xc = ((const float4*)(base + 0 * NA))[j];
    const float4 yc = ((const float4*)(base + 1 * NA))[j];
    const float4 ww = ((const float4*)(base + 2 * NA))[j];
    const float4 hh = ((const float4*)(base + 3 * NA))[j];

    float4 best = make_float4(-FLT_MAX, -FLT_MAX, -FLT_MAX, -FLT_MAX);
    int4   cls  = make_int4(0, 0, 0, 0);
    #pragma unroll
    for (int k = 0; k < NC; ++k) {
        float4 v = ((const float4*)(base + (4 + k) * NA))[j];
        if (v.x > best.x) { best.x = v.x; cls.x = k; }
        if (v.y > best.y) { best.y = v.y; cls.y = k; }
        if (v.z > best.z) { best.z = v.z; cls.z = k; }
        if (v.w > best.w) { best.w = v.w; cls.w = k; }
    }

    const int a0 = 4 * j;
    float4* ob = g_box + (size_t)b * NA + a0;
    float h2, w2;
    h2 = hh.x * 0.5f; w2 = ww.x * 0.5f;
    ob[0] = make_float4(fminf(fmaxf(yc.x - h2, 0.f), 1.f), fminf(fmaxf(xc.x - w2, 0.f), 1.f),
                        fminf(fmaxf(yc.x + h2, 0.f), 1.f), fminf(fmaxf(xc.x + w2, 0.f), 1.f));
    h2 = hh.y * 0.5f; w2 = ww.y * 0.5f;
    ob[1] = make_float4(fminf(fmaxf(yc.y - h2, 0.f), 1.f), fminf(fmaxf(xc.y - w2, 0.f), 1.f),
                        fminf(fmaxf(yc.y + h2, 0.f), 1.f), fminf(fmaxf(xc.y + w2, 0.f), 1.f));
    h2 = hh.z * 0.5f; w2 = ww.z * 0.5f;
    ob[2] = make_float4(fminf(fmaxf(yc.z - h2, 0.f), 1.f), fminf(fmaxf(xc.z - w2, 0.f), 1.f),
                        fminf(fmaxf(yc.z + h2, 0.f), 1.f), fminf(fmaxf(xc.z + w2, 0.f), 1.f));
    h2 = hh.w * 0.5f; w2 = ww.w * 0.5f;
    ob[3] = make_float4(fminf(fmaxf(yc.w - h2, 0.f), 1.f), fminf(fmaxf(xc.w - w2, 0.f), 1.f),
                        fminf(fmaxf(yc.w + h2, 0.f), 1.f), fminf(fmaxf(xc.w + w2, 0.f), 1.f));

    float4 sc;
    sc.x = (best.x >= CONF_T) ? best.x : -1.0f;
    sc.y = (best.y >= CONF_T) ? best.y : -1.0f;
    sc.z = (best.z >= CONF_T) ? best.z : -1.0f;
    sc.w = (best.w >= CONF_T) ? best.w : -1.0f;
    *(float4*)(g_sc + (size_t)b * NA + a0) = sc;
    *(uchar4*)(g_cls + (size_t)b * NA + a0) =
        make_uchar4((unsigned char)cls.x, (unsigned char)cls.y,
                    (unsigned char)cls.z, (unsigned char)cls.w);
}

__device__ __forceinline__ int wsuffix(int v, int lane)
{
    #pragma unroll
    for (int off = 1; off < 32; off <<= 1) {
        int o = __shfl_down_sync(FULLM, v, off);
        if (lane + off < 32) v += o;
    }
    return v;
}

// ---------------- Kernel 2: sorted-scan NMS ----------------
__global__ __launch_bounds__(NT2, 1)
void nms_kernel(float* __restrict__ out)
{
    extern __shared__ unsigned char sm[];
    float4*             s_box  = (float4*)sm;
    float*              s_area = (float*)(sm + OFF_AREA);
    unsigned char*      s_cls  = sm + OFF_CLS;
    unsigned long long* s_k    = (unsigned long long*)(sm + OFF_K64);
    int*                s_hist = (int*)(sm + OFF_HIST);
    float4*             s_accb = (float4*)(sm + OFF_ACCB);
    float*              s_acca = (float*)(sm + OFF_ACCA);

    __shared__ int s_gc, s_blo, s_total, s_accn;
    __shared__ unsigned s_kmask[32];
    __shared__ int      s_kflag[32];

    const int b    = blockIdx.x;
    const int tid  = threadIdx.x;
    const int lane = tid & 31;
    const int w    = tid >> 5;

    float* out_boxes = out;
    float* out_cls   = out + (size_t)NB * MAXD * 4;
    float* out_scr   = out_cls + (size_t)NB * MAXD;
    float* out_num   = out_scr + (size_t)NB * MAXD;

    // ---- load + one-time histogram ----
    for (int i = tid; i < NBINS; i += NT2) s_hist[i] = 0;
    int key[NSLOT];
    const size_t off = (size_t)b * NA;
    #pragma unroll
    for (int k = 0; k < NSLOT; ++k) {
        const int a = tid + (k << 10);
        if (a < NA) {
            float4 f4 = g_box[off + a];
            s_box[a]  = f4;
            s_area[a] = (f4.z - f4.x) * (f4.w - f4.y);
            s_cls[a]  = g_cls[off + a];
            key[k]    = __float_as_int(g_sc[off + a]);
        } else {
            key[k] = __float_as_int(-1.0f);
        }
    }
    if (tid == 0) s_accn = 0;
    __syncthreads();
    #pragma unroll
    for (int k = 0; k < NSLOT; ++k) {
        if (key[k] >= BASEKEY) {
            int bin = (key[k] - BASEKEY) >> 13;
            if (bin > NBINS - 1) bin = NBINS - 1;
            atomicAdd(&s_hist[bin], 1);
        }
    }
    int Uprev_bin = NBINS;
    __syncthreads();

    for (;;) {
        // ---- selection from persistent histogram, bins < Uprev_bin only ----
        if (w == 0) {
            int sA = 0, sB = 0;
            #pragma unroll 4
            for (int i = 0; i < 32; ++i) {
                const int ia = 1024 + lane * 32 + i;
                const int ib = lane * 32 + i;
                sA += (ia < Uprev_bin) ? s_hist[ia] : 0;
                sB += (ib < Uprev_bin) ? s_hist[ib] : 0;
            }
            int sufA = wsuffix(sA, lane);
            int totalHigh = __shfl_sync(FULLM, sufA, 0);
            int sufB = wsuffix(sB, lane) + totalHigh;
            int total = __shfl_sync(FULLM, sufB, 0);

            int b_lo = 0, cnt = total;
            if (total > 0) {
                unsigned ballB = __ballot_sync(FULLM, sufB <= CAP);
                unsigned ballA = __ballot_sync(FULLM, sufA <= CAP);
                int cstar;
                if (ballB) cstar = __ffs(ballB) - 1;
                else if (ballA) cstar = 32 + __ffs(ballA) - 1;
                else cstar = 64;
                int csufstar = 0;
                if (cstar < 32)      csufstar = __shfl_sync(FULLM, sufB, cstar);
                else if (cstar < 64) csufstar = __shfl_sync(FULLM, sufA, cstar - 32);
                if (cstar == 0) { b_lo = 0; cnt = total; }
                else {
                    const int c = cstar - 1;
                    const int bi = c * 32 + lane;
                    int v = (bi < Uprev_bin) ? s_hist[bi] : 0;
                    int suf = wsuffix(v, lane) + csufstar;
                    unsigned bb = __ballot_sync(FULLM, suf <= CAP);
                    if (bb) {
                        int l = __ffs(bb) - 1;
                        b_lo = c * 32 + l;
                        cnt  = __shfl_sync(FULLM, suf, l);
                    } else {
                        b_lo = c * 32 + 32;
                        cnt  = csufstar;
                    }
                }
                if (cnt == 0) {
                    unsigned nzA = __ballot_sync(FULLM, sA > 0);
                    unsigned nzB = __ballot_sync(FULLM, sB > 0);
                    int c = nzA ? (32 + 31 - __clz(nzA)) : (31 - __clz(nzB));
                    const int bi = c * 32 + lane;
                    int v = (bi < Uprev_bin) ? s_hist[bi] : 0;
                    unsigned nz = __ballot_sync(FULLM, v > 0);
                    b_lo = c * 32 + (31 - __clz(nz));
                    cnt  = CAP;
                }
            }
            if (lane == 0) { s_blo = b_lo; s_total = total; s_gc = 0; }
        }
        __syncthreads();

        if (s_total == 0) break;
        const int b_lo = s_blo;

        // ---- gather tranche: bins in [b_lo, Uprev_bin) ----
        #pragma unroll
        for (int k = 0; k < NSLOT; ++k) {
            if (key[k] >= BASEKEY) {
                int bin = (key[k] - BASEKEY) >> 13;
                if (bin > NBINS - 1) bin = NBINS - 1;
                if (bin >= b_lo && bin < Uprev_bin) {
                    int pos = atomicAdd(&s_gc, 1);
                    if (pos < CAP) {
                        const int a = tid + (k << 10);
                        const unsigned u = (unsigned)key[k] ^ 0x80000000u;
                        s_k[pos] = ((unsigned long long)(~u) << 32) | (unsigned)a;
                    }
                }
            }
        }
        __syncthreads();
        int g = s_gc; if (g > CAP) g = CAP;

        // ---- pad + bitonic sort (warp-scope sync for j<32 stages) ----
        int S = 1; while (S < g) S <<= 1;
        for (int i = g + tid; i < S; i += NT2) s_k[i] = 0xFFFFFFFFFFFFFFFFull;
        __syncthreads();
        for (int kk = 2; kk <= S; kk <<= 1) {
            int j = kk >> 1;
            for (; j >= 32; j >>= 1) {            // cross-warp stages
                const int i = tid;
                if (i < S) {
                    const int ixj = i ^ j;
                    if (ixj > i) {
                        unsigned long long A = s_k[i], B = s_k[ixj];
                        const bool up = ((i & kk) == 0);
                        if ((A > B) == up) { s_k[i] = B; s_k[ixj] = A; }
                    }
                }
                __syncthreads();
            }
            for (; j > 0; j >>= 1) {              // warp-local stages
                const int i = tid;
                if (i < S) {
                    const int ixj = i ^ j;
                    if (ixj > i) {
                        unsigned long long A = s_k[i], B = s_k[ixj];
                        const bool up = ((i & kk) == 0);
                        if ((A > B) == up) { s_k[i] = B; s_k[ixj] = A; }
                    }
                }
                __syncwarp();
            }
            __syncthreads();
        }

        // ---- chunked scan: 32 candidates per step ----
        for (int cb0 = 0; cb0 < g; cb0 += 32) {
            const int accL = s_accn;
            if (accL >= MAXD) break;
            const int rem    = g - cb0;
            const bool havec  = (w < rem);
            const bool lvalid = (lane < rem);

            unsigned long long kl = 0; int idxl = 0;
            float4 lb = make_float4(0, 0, 0, 0); float la = 0.f;
            if (lvalid) {
                kl   = s_k[cb0 + lane];
                idxl = (int)(unsigned)(kl & 0xFFFFFFFFull);
                lb   = s_box[idxl];
                la   = s_area[idxl];
            }

            if (havec) {
                const unsigned long long kw = s_k[cb0 + w];
                const int    idxw = (int)(unsigned)(kw & 0xFFFFFFFFull);
                const float4 cbx  = s_box[idxw];
                const float  caw  = s_area[idxw];

                int pred = 0;
                #pragma unroll
                for (int t = 0; t < 4; ++t) {
                    if (t * 32 < accL) {
                        const int a = lane + t * 32;
                        if (a < accL) {
                            const float4 A = s_accb[a];
                            const float  aa = s_acca[a];
                            float y1 = fmaxf(A.x, cbx.x);
                            float x1 = fmaxf(A.y, cbx.y);
                            float y2 = fminf(A.z, cbx.z);
                            float x2 = fminf(A.w, cbx.w);
                            float inter = fmaxf(y2 - y1, 0.0f) * fmaxf(x2 - x1, 0.0f);
                            float uni   = aa + caw - inter;
                            float iou   = (uni > 0.0f) ? (inter / uni) : 0.0f;
                            pred |= (iou > IOU_T) ? 1 : 0;
                        }
                        if (__any_sync(FULLM, pred)) break;   // uniform early exit
                    }
                }
                int mpred = 0;
                if (lvalid && lane != w) {
                    float y1 = fmaxf(cbx.x, lb.x);
                    float x1 = fmaxf(cbx.y, lb.y);
                    float y2 = fminf(cbx.z, lb.z);
                    float x2 = fminf(cbx.w, lb.w);
                    float inter = fmaxf(y2 - y1, 0.0f) * fmaxf(x2 - x1, 0.0f);
                    float uni   = caw + la - inter;
                    float iou   = (uni > 0.0f) ? (inter / uni) : 0.0f;
                    mpred = (iou > IOU_T) ? 1 : 0;
                }
                const unsigned kb = __ballot_sync(FULLM, pred != 0);
                const unsigned mw = __ballot_sync(FULLM, mpred != 0);
                if (lane == 0) { s_kmask[w] = mw; s_kflag[w] = (kb != 0) ? 1 : 0; }
            }
            __syncthreads();

            if (w == 0) {
                const unsigned mask_l = s_kmask[lane];
                const int      kf     = s_kflag[lane];
                const unsigned killword = __ballot_sync(FULLM, kf != 0);
                const unsigned validw = (rem >= 32) ? FULLM : ((1u << rem) - 1u);
                unsigned avail  = ~(killword | ~validw);   // alive candidate bits
                unsigned accept = 0;
                int na = accL;
                while (avail) {                            // iterations == accepts
                    const int i = __ffs(avail) - 1;        // lowest index = sorted order
                    accept |= (1u << i);
                    ++na;
                    if (na == MAXD) break;
                    const unsigned mi = __shfl_sync(FULLM, mask_l, i);
                    avail &= ~mi;
                    avail &= ~(1u << i);
                }
                if ((accept >> lane) & 1u) {
                    const int pos = accL + __popc(accept & ((1u << lane) - 1u));
                    s_accb[pos] = lb;
                    s_acca[pos] = la;
                    float* ob = out_boxes + ((size_t)b * MAXD + pos) * 4;
                    ob[0] = lb.x; ob[1] = lb.y; ob[2] = lb.z; ob[3] = lb.w;
                    const unsigned um = ~(unsigned)(kl >> 32);
                    out_scr[(size_t)b * MAXD + pos] = __int_as_float((int)(um ^ 0x80000000u));
                    out_cls[(size_t)b * MAXD + pos] = (float)s_cls[idxl];
                }
                if (lane == 0) s_accn = na;
            }
            __syncthreads();
        }

        if (s_accn >= MAXD) break;
        Uprev_bin = b_lo;
        if (Uprev_bin == 0) break;
    }

    const int acc = s_accn;
    for (int i = acc * 4 + tid; i < MAXD * 4; i += NT2)
        out_boxes[(size_t)b * MAXD * 4 + i] = 0.0f;
    for (int i = acc + tid; i < MAXD; i += NT2) {
        out_cls[(size_t)b * MAXD + i] = 0.0f;
        out_scr[(size_t)b * MAXD + i] = 0.0f;
    }
    if (tid == 0) out_num[b] = (float)acc;
}

extern "C" void kernel_launch(void* const* d_in, const int* in_sizes, int n_in,
                              void* d_out, int out_size)
{
    (void)in_sizes; (void)n_in; (void)out_size;
    const float* in = (const float*)d_in[0];
    float* out = (float*)d_out;

    dim3 g1((NJ + NT1 - 1) / NT1, NB);
    decode_kernel<<<g1, NT1>>>(in);

    cudaFuncSetAttribute(nms_kernel,
                         cudaFuncAttributeMaxDynamicSharedMemorySize,
                         (int)SMEM2_BYTES);
    nms_kernel<<<NB, NT2, SMEM2_BYTES>>>(out);
}

// round 17
// speedup vs baseline: 1.5074x; 1.5074x over previous
#include <cuda_runtime.h>
#include <float.h>

#define NA 8400
#define NB 64
#define NC 32
#define MAXD 100
#define CONF_T 0.25f
#define IOU_T 0.45f

#define NT1 256
#define NJ (NA / 4)

#define NT2 1024
#define NSLOT 9
#define CAP 512
#define NBINS 2048
#define BASEKEY 0x3E800000   // bits of 0.25f
#define FULLM 0xffffffffu

__device__ float4        g_box[NB * NA];
__device__ float         g_sc [NB * NA];
__device__ unsigned char g_cls[NB * NA];

// dynamic smem: float4 box[NA] | float area[NA] | u8 cls[NA] | u64 k[CAP] | int hist[NBINS]
//               | float4 accb[128] | float acca[128]
#define OFF_AREA (NA * 16)
#define OFF_CLS  (OFF_AREA + NA * 4)
#define OFF_K64  (OFF_CLS + NA)
#define OFF_HIST (OFF_K64 + CAP * 8)
#define OFF_ACCB (OFF_HIST + NBINS * 4)
#define OFF_ACCA (OFF_ACCB + 128 * 16)
#define SMEM2_BYTES (OFF_ACCA + 128 * 4)

// ---------------- Kernel 1: decode (unchanged; at memory roofline) ----------------
__global__ __launch_bounds__(NT1)
void decode_kernel(const float* __restrict__ in)
{
    const int j = blockIdx.x * NT1 + threadIdx.x;
    const int b = blockIdx.y;
    if (j >= NJ) return;
    const float* base = in + (size_t)b * (4 + NC) * NA;

    const float4 xc = ((const float4*)(base + 0 * NA))[j];
    const float4 yc = ((const float4*)(base + 1 * NA))[j];
    const float4 ww = ((const float4*)(base + 2 * NA))[j];
    const float4 hh = ((const float4*)(base + 3 * NA))[j];

    float4 best = make_float4(-FLT_MAX, -FLT_MAX, -FLT_MAX, -FLT_MAX);
    int4   cls  = make_int4(0, 0, 0, 0);
    #pragma unroll
    for (int k = 0; k < NC; ++k) {
        float4 v = ((const float4*)(base + (4 + k) * NA))[j];
        if (v.x > best.x) { best.x = v.x; cls.x = k; }
        if (v.y > best.y) { best.y = v.y; cls.y = k; }
        if (v.z > best.z) { best.z = v.z; cls.z = k; }
        if (v.w > best.w) { best.w = v.w; cls.w = k; }
    }

    const int a0 = 4 * j;
    float4* ob = g_box + (size_t)b * NA + a0;
    float h2, w2;
    h2 = hh.x * 0.5f; w2 = ww.x * 0.5f;
    ob[0] = make_float4(fminf(fmaxf(yc.x - h2, 0.f), 1.f), fminf(fmaxf(xc.x - w2, 0.f), 1.f),
                        fminf(fmaxf(yc.x + h2, 0.f), 1.f), fminf(fmaxf(xc.x + w2, 0.f), 1.f));
    h2 = hh.y * 0.5f; w2 = ww.y * 0.5f;
    ob[1] = make_float4(fminf(fmaxf(yc.y - h2, 0.f), 1.f), fminf(fmaxf(xc.y - w2, 0.f), 1.f),
                        fminf(fmaxf(yc.y + h2, 0.f), 1.f), fminf(fmaxf(xc.y + w2, 0.f), 1.f));
    h2 = hh.z * 0.5f; w2 = ww.z * 0.5f;
    ob[2] = make_float4(fminf(fmaxf(yc.z - h2, 0.f), 1.f), fminf(fmaxf(xc.z - w2, 0.f), 1.f),
                        fminf(fmaxf(yc.z + h2, 0.f), 1.f), fminf(fmaxf(xc.z + w2, 0.f), 1.f));
    h2 = hh.w * 0.5f; w2 = ww.w * 0.5f;
    ob[3] = make_float4(fminf(fmaxf(yc.w - h2, 0.f), 1.f), fminf(fmaxf(xc.w - w2, 0.f), 1.f),
                        fminf(fmaxf(yc.w + h2, 0.f), 1.f), fminf(fmaxf(xc.w + w2, 0.f), 1.f));

    float4 sc;
    sc.x = (best.x >= CONF_T) ? best.x : -1.0f;
    sc.y = (best.y >= CONF_T) ? best.y : -1.0f;
    sc.z = (best.z >= CONF_T) ? best.z : -1.0f;
    sc.w = (best.w >= CONF_T) ? best.w : -1.0f;
    *(float4*)(g_sc + (size_t)b * NA + a0) = sc;
    *(uchar4*)(g_cls + (size_t)b * NA + a0) =
        make_uchar4((unsigned char)cls.x, (unsigned char)cls.y,
                    (unsigned char)cls.z, (unsigned char)cls.w);
}

__device__ __forceinline__ int wsuffix(int v, int lane)
{
    #pragma unroll
    for (int off = 1; off < 32; off <<= 1) {
        int o = __shfl_down_sync(FULLM, v, off);
        if (lane + off < 32) v += o;
    }
    return v;
}

// ---------------- Kernel 2: sorted-scan NMS ----------------
__global__ __launch_bounds__(NT2, 1)
void nms_kernel(float* __restrict__ out)
{
    extern __shared__ unsigned char sm[];
    float4*             s_box  = (float4*)sm;
    float*              s_area = (float*)(sm + OFF_AREA);
    unsigned char*      s_cls  = sm + OFF_CLS;
    unsigned long long* s_k    = (unsigned long long*)(sm + OFF_K64);
    int*                s_hist = (int*)(sm + OFF_HIST);
    float4*             s_accb = (float4*)(sm + OFF_ACCB);
    float*              s_acca = (float*)(sm + OFF_ACCA);

    __shared__ int s_gc, s_blo, s_total, s_accn;
    __shared__ unsigned s_kmask[32];
    __shared__ int      s_kflag[32];

    const int b    = blockIdx.x;
    const int tid  = threadIdx.x;
    const int lane = tid & 31;
    const int w    = tid >> 5;

    float* out_boxes = out;
    float* out_cls   = out + (size_t)NB * MAXD * 4;
    float* out_scr   = out_cls + (size_t)NB * MAXD;
    float* out_num   = out_scr + (size_t)NB * MAXD;

    // ---- load + one-time histogram ----
    for (int i = tid; i < NBINS; i += NT2) s_hist[i] = 0;
    int key[NSLOT];
    const size_t off = (size_t)b * NA;
    #pragma unroll
    for (int k = 0; k < NSLOT; ++k) {
        const int a = tid + (k << 10);
        if (a < NA) {
            float4 f4 = g_box[off + a];
            s_box[a]  = f4;
            s_area[a] = (f4.z - f4.x) * (f4.w - f4.y);
            s_cls[a]  = g_cls[off + a];
            key[k]    = __float_as_int(g_sc[off + a]);
        } else {
            key[k] = __float_as_int(-1.0f);
        }
    }
    if (tid == 0) s_accn = 0;
    __syncthreads();
    #pragma unroll
    for (int k = 0; k < NSLOT; ++k) {
        if (key[k] >= BASEKEY) {
            int bin = (key[k] - BASEKEY) >> 13;
            if (bin > NBINS - 1) bin = NBINS - 1;
            atomicAdd(&s_hist[bin], 1);
        }
    }
    int Uprev_bin = NBINS;
    __syncthreads();

    for (;;) {
        // ---- selection from persistent histogram, bins < Uprev_bin only ----
        if (w == 0) {
            int sA = 0, sB = 0;
            #pragma unroll 4
            for (int i = 0; i < 32; ++i) {
                const int ia = 1024 + lane * 32 + i;
                const int ib = lane * 32 + i;
                sA += (ia < Uprev_bin) ? s_hist[ia] : 0;
                sB += (ib < Uprev_bin) ? s_hist[ib] : 0;
            }
            int sufA = wsuffix(sA, lane);
            int totalHigh = __shfl_sync(FULLM, sufA, 0);
            int sufB = wsuffix(sB, lane) + totalHigh;
            int total = __shfl_sync(FULLM, sufB, 0);

            int b_lo = 0, cnt = total;
            if (total > 0) {
                unsigned ballB = __ballot_sync(FULLM, sufB <= CAP);
                unsigned ballA = __ballot_sync(FULLM, sufA <= CAP);
                int cstar;
                if (ballB) cstar = __ffs(ballB) - 1;
                else if (ballA) cstar = 32 + __ffs(ballA) - 1;
                else cstar = 64;
                int csufstar = 0;
                if (cstar < 32)      csufstar = __shfl_sync(FULLM, sufB, cstar);
                else if (cstar < 64) csufstar = __shfl_sync(FULLM, sufA, cstar - 32);
                if (cstar == 0) { b_lo = 0; cnt = total; }
                else {
                    const int c = cstar - 1;
                    const int bi = c * 32 + lane;
                    int v = (bi < Uprev_bin) ? s_hist[bi] : 0;
                    int suf = wsuffix(v, lane) + csufstar;
                    unsigned bb = __ballot_sync(FULLM, suf <= CAP);
                    if (bb) {
                        int l = __ffs(bb) - 1;
                        b_lo = c * 32 + l;
                        cnt  = __shfl_sync(FULLM, suf, l);
                    } else {
                        b_lo = c * 32 + 32;
                        cnt  = csufstar;
                    }
                }
                if (cnt == 0) {
                    unsigned nzA = __ballot_sync(FULLM, sA > 0);
                    unsigned nzB = __ballot_sync(FULLM, sB > 0);
                    int c = nzA ? (32 + 31 - __clz(nzA)) : (31 - __clz(nzB));
                    const int bi = c * 32 + lane;
                    int v = (bi < Uprev_bin) ? s_hist[bi] : 0;
                    unsigned nz = __ballot_sync(FULLM, v > 0);
                    b_lo = c * 32 + (31 - __clz(nz));
                    cnt  = CAP;
                }
            }
            if (lane == 0) { s_blo = b_lo; s_total = total; s_gc = 0; }
        }
        __syncthreads();

        if (s_total == 0) break;
        const int b_lo = s_blo;

        // ---- gather tranche: bins in [b_lo, Uprev_bin) ----
        #pragma unroll
        for (int k = 0; k < NSLOT; ++k) {
            if (key[k] >= BASEKEY) {
                int bin = (key[k] - BASEKEY) >> 13;
                if (bin > NBINS - 1) bin = NBINS - 1;
                if (bin >= b_lo && bin < Uprev_bin) {
                    int pos = atomicAdd(&s_gc, 1);
                    if (pos < CAP) {
                        const int a = tid + (k << 10);
                        const unsigned u = (unsigned)key[k] ^ 0x80000000u;
                        s_k[pos] = ((unsigned long long)(~u) << 32) | (unsigned)a;
                    }
                }
            }
        }
        __syncthreads();
        int g = s_gc; if (g > CAP) g = CAP;

        // ---- pad + bitonic sort (warp-scope sync for j<32 stages) ----
        int S = 1; while (S < g) S <<= 1;
        for (int i = g + tid; i < S; i += NT2) s_k[i] = 0xFFFFFFFFFFFFFFFFull;
        __syncthreads();
        for (int kk = 2; kk <= S; kk <<= 1) {
            int j = kk >> 1;
            for (; j >= 32; j >>= 1) {            // cross-warp stages
                const int i = tid;
                if (i < S) {
                    const int ixj = i ^ j;
                    if (ixj > i) {
                        unsigned long long A = s_k[i], B = s_k[ixj];
                        const bool up = ((i & kk) == 0);
                        if ((A > B) == up) { s_k[i] = B; s_k[ixj] = A; }
                    }
                }
                __syncthreads();
            }
            for (; j > 0; j >>= 1) {              // warp-local stages
                const int i = tid;
                if (i < S) {
                    const int ixj = i ^ j;
                    if (ixj > i) {
                        unsigned long long A = s_k[i], B = s_k[ixj];
                        const bool up = ((i & kk) == 0);
                        if ((A > B) == up) { s_k[i] = B; s_k[ixj] = A; }
                    }
                }
                __syncwarp();
            }
            __syncthreads();
        }

        // ---- chunked scan: 32 candidates per step (phase A = R13, NO early exit) ----
        for (int cb0 = 0; cb0 < g; cb0 += 32) {
            const int accL = s_accn;
            if (accL >= MAXD) break;
            const int rem    = g - cb0;
            const bool havec  = (w < rem);
            const bool lvalid = (lane < rem);

            unsigned long long kl = 0; int idxl = 0;
            float4 lb = make_float4(0, 0, 0, 0); float la = 0.f;
            if (lvalid) {
                kl   = s_k[cb0 + lane];
                idxl = (int)(unsigned)(kl & 0xFFFFFFFFull);
                lb   = s_box[idxl];
                la   = s_area[idxl];
            }

            if (havec) {
                const unsigned long long kw = s_k[cb0 + w];
                const int    idxw = (int)(unsigned)(kw & 0xFFFFFFFFull);
                const float4 cbx  = s_box[idxw];
                const float  caw  = s_area[idxw];

                int pred = 0;
                #pragma unroll
                for (int t = 0; t < 4; ++t) {
                    if (t * 32 < accL) {
                        const int a = lane + t * 32;
                        if (a < accL) {
                            const float4 A = s_accb[a];
                            const float  aa = s_acca[a];
                            float y1 = fmaxf(A.x, cbx.x);
                            float x1 = fmaxf(A.y, cbx.y);
                            float y2 = fminf(A.z, cbx.z);
                            float x2 = fminf(A.w, cbx.w);
                            float inter = fmaxf(y2 - y1, 0.0f) * fmaxf(x2 - x1, 0.0f);
                            float uni   = aa + caw - inter;
                            float iou   = (uni > 0.0f) ? (inter / uni) : 0.0f;
                            pred |= (iou > IOU_T) ? 1 : 0;
                        }
                    }
                }
                int mpred = 0;
                if (lvalid && lane != w) {
                    float y1 = fmaxf(cbx.x, lb.x);
                    float x1 = fmaxf(cbx.y, lb.y);
                    float y2 = fminf(cbx.z, lb.z);
                    float x2 = fminf(cbx.w, lb.w);
                    float inter = fmaxf(y2 - y1, 0.0f) * fmaxf(x2 - x1, 0.0f);
                    float uni   = caw + la - inter;
                    float iou   = (uni > 0.0f) ? (inter / uni) : 0.0f;
                    mpred = (iou > IOU_T) ? 1 : 0;
                }
                const unsigned kb = __ballot_sync(FULLM, pred != 0);
                const unsigned mw = __ballot_sync(FULLM, mpred != 0);
                if (lane == 0) { s_kmask[w] = mw; s_kflag[w] = (kb != 0) ? 1 : 0; }
            }
            __syncthreads();

            // Phase B (warp 0): ffs-driven resolve — iterations == accepts
            if (w == 0) {
                const unsigned mask_l = s_kmask[lane];
                const int      kf     = s_kflag[lane];
                const unsigned killword = __ballot_sync(FULLM, kf != 0);
                const unsigned validw = (rem >= 32) ? FULLM : ((1u << rem) - 1u);
                unsigned avail  = ~(killword | ~validw);
                unsigned accept = 0;
                int na = accL;
                while (avail) {
                    const int i = __ffs(avail) - 1;        // lowest index = sorted order
                    accept |= (1u << i);
                    ++na;
                    if (na == MAXD) break;
                    const unsigned mi = __shfl_sync(FULLM, mask_l, i);
                    avail &= ~(mi | (1u << i));
                }
                if ((accept >> lane) & 1u) {
                    const int pos = accL + __popc(accept & ((1u << lane) - 1u));
                    s_accb[pos] = lb;
                    s_acca[pos] = la;
                    float* ob = out_boxes + ((size_t)b * MAXD + pos) * 4;
                    ob[0] = lb.x; ob[1] = lb.y; ob[2] = lb.z; ob[3] = lb.w;
                    const unsigned um = ~(unsigned)(kl >> 32);
                    out_scr[(size_t)b * MAXD + pos] = __int_as_float((int)(um ^ 0x80000000u));
                    out_cls[(size_t)b * MAXD + pos] = (float)s_cls[idxl];
                }
                if (lane == 0) s_accn = na;
            }
            __syncthreads();
        }

        if (s_accn >= MAXD) break;
        Uprev_bin = b_lo;
        if (Uprev_bin == 0) break;
    }

    const int acc = s_accn;
    for (int i = acc * 4 + tid; i < MAXD * 4; i += NT2)
        out_boxes[(size_t)b * MAXD * 4 + i] = 0.0f;
    for (int i = acc + tid; i < MAXD; i += NT2) {
        out_cls[(size_t)b * MAXD + i] = 0.0f;
        out_scr[(size_t)b * MAXD + i] = 0.0f;
    }
    if (tid == 0) out_num[b] = (float)acc;
}

extern "C" void kernel_launch(void* const* d_in, const int* in_sizes, int n_in,
                              void* d_out, int out_size)
{
    (void)in_sizes; (void)n_in; (void)out_size;
    const float* in = (const float*)d_in[0];
    float* out = (float*)d_out;

    dim3 g1((NJ + NT1 - 1) / NT1, NB);
    decode_kernel<<<g1, NT1>>>(in);

    cudaFuncSetAttribute(nms_kernel,
                         cudaFuncAttributeMaxDynamicSharedMemorySize,
                         (int)SMEM2_BYTES);
    nms_kernel<<<NB, NT2, SMEM2_BYTES>>>(out);
}